// round 6
// baseline (speedup 1.0000x reference)
#include <cuda_runtime.h>
#include <mma.h>
#include <math.h>

using namespace nvcuda;

// ---------------------------------------------------------------------------
// MemoryGatedAttention  (B=4, T=S=2048, D=1024, H=16, DH=64, M=64)
// Round 4 (re-bench of R3 after infra failure):
//   tf32 wmma + cp.async double buffering; 128-row flash tile.
// ---------------------------------------------------------------------------

namespace cfg {
constexpr int B  = 4;
constexpr int T  = 2048;
constexpr int S  = 2048;
constexpr int D  = 1024;
constexpr int H  = 16;
constexpr int DH = 64;
constexpr int M  = 64;
constexpr int BT = B * T;
constexpr int FL_LD = 68;          // smem row stride (floats)
// flash smem floats: Ks[2][64][68] + Vs[2][64][68] + Ss[128][68] + stats + idx
constexpr int FL_KS = 2 * 64 * FL_LD;              // 8704
constexpr int FL_VS = 2 * 64 * FL_LD;              // 8704
constexpr int FL_SS = 128 * FL_LD;                 // 8704
constexpr int FL_SMEM_FLOATS = FL_KS + FL_VS + FL_SS + 3 * 128 + 256;
constexpr int FL_SMEM = FL_SMEM_FLOATS * (int)sizeof(float);   // ~107KB
}

// ----------------------------- scratch --------------------------------------
__device__ float g_Q[cfg::B * cfg::T * cfg::D];
__device__ float g_K[cfg::B * cfg::S * cfg::D];
__device__ float g_V[cfg::B * cfg::S * cfg::D];
__device__ float g_O[cfg::B * cfg::T * cfg::D];
__device__ float g_memin[cfg::B * 2 * cfg::D];
__device__ float g_gatevals[cfg::B * cfg::D];
__device__ float g_scale_val;

// ----------------------------- cp.async helpers ------------------------------
__device__ __forceinline__ void cp_async16(void* smem_dst, const void* gmem_src) {
    unsigned sa = (unsigned)__cvta_generic_to_shared(smem_dst);
    asm volatile("cp.async.cg.shared.global [%0], [%1], 16;\n" :: "r"(sa), "l"(gmem_src));
}
__device__ __forceinline__ void cp_commit() {
    asm volatile("cp.async.commit_group;\n");
}
template <int N>
__device__ __forceinline__ void cp_wait() {
    asm volatile("cp.async.wait_group %0;\n" :: "n"(N));
}

// ----------------------------- fragment types --------------------------------
using FragA  = wmma::fragment<wmma::matrix_a, 16, 16, 8, wmma::precision::tf32, wmma::row_major>;
using FragBr = wmma::fragment<wmma::matrix_b, 16, 16, 8, wmma::precision::tf32, wmma::row_major>;
using FragBc = wmma::fragment<wmma::matrix_b, 16, 16, 8, wmma::precision::tf32, wmma::col_major>;
using FragC  = wmma::fragment<wmma::accumulator, 16, 16, 8, float>;

template <typename F>
__device__ __forceinline__ void to_tf32(F& f) {
#pragma unroll
    for (int e = 0; e < f.num_elements; e++) f.x[e] = wmma::__float_to_tf32(f.x[e]);
}

// ----------------------------- means ----------------------------------------
__global__ void __launch_bounds__(256)
mean_kernel(const float* __restrict__ query, const float* __restrict__ memory)
{
    using namespace cfg;
    const int b = blockIdx.y;
    const int d = blockIdx.x * blockDim.x + threadIdx.x;

    const float* qp = query + (size_t)b * T * D + d;
    float s0 = 0.f, s1 = 0.f, s2 = 0.f, s3 = 0.f;
    for (int t = 0; t < T; t += 4) {
        s0 += qp[(size_t)(t + 0) * D];
        s1 += qp[(size_t)(t + 1) * D];
        s2 += qp[(size_t)(t + 2) * D];
        s3 += qp[(size_t)(t + 3) * D];
    }
    g_memin[b * 2 * D + d] = ((s0 + s1) + (s2 + s3)) * (1.0f / T);

    const float* mp = memory + (size_t)b * M * D + d;
    float u0 = 0.f, u1 = 0.f;
    for (int m = 0; m < M; m += 2) {
        u0 += mp[(size_t)(m + 0) * D];
        u1 += mp[(size_t)(m + 1) * D];
    }
    g_memin[b * 2 * D + D + d] = (u0 + u1) * (1.0f / M);
}

// ----------------------------- gate ------------------------------------------
__global__ void __launch_bounds__(256)
gate_vals_kernel(const float* __restrict__ Wg, const float* __restrict__ bg)
{
    using namespace cfg;
    const int b = blockIdx.y;
    const int j = blockIdx.x * blockDim.x + threadIdx.x;
    const float* mi = g_memin + b * 2 * D;

    float a0 = 0.f, a1 = 0.f, a2 = 0.f, a3 = 0.f;
    for (int i = 0; i < 2 * D; i += 4) {
        a0 += mi[i + 0] * Wg[(size_t)(i + 0) * D + j];
        a1 += mi[i + 1] * Wg[(size_t)(i + 1) * D + j];
        a2 += mi[i + 2] * Wg[(size_t)(i + 2) * D + j];
        a3 += mi[i + 3] * Wg[(size_t)(i + 3) * D + j];
    }
    float acc = bg[j] + ((a0 + a1) + (a2 + a3));
    g_gatevals[b * D + j] = 1.0f / (1.0f + expf(-acc));
}

__global__ void gate_reduce_kernel()
{
    using namespace cfg;
    __shared__ float red[1024];
    const int t = threadIdx.x;
    red[t] = g_gatevals[t] + g_gatevals[t + 1024] +
             g_gatevals[t + 2048] + g_gatevals[t + 3072];
    __syncthreads();
    for (int s = 512; s > 0; s >>= 1) {
        if (t < s) red[t] += red[t + s];
        __syncthreads();
    }
    if (t == 0) g_scale_val = red[0] * (1.0f / (B * D)) * 0.125f;
}

// ----------------------------- tf32 GEMM body (double-buffered) --------------
// C = A[8192,1024] @ W[1024,1024] + bias.  128x128x16 tile, 8 warps (2x4).
__device__ __forceinline__ void gemm_body(
    const float* __restrict__ A, const float* __restrict__ W,
    const float* __restrict__ bias, float* __restrict__ C)
{
    using namespace cfg;
    __shared__ float As[2][128][20];
    __shared__ float Bs[2][16][132];
    __shared__ float idxm[256];

    const int tid = threadIdx.x;
    const int warpId = tid >> 5;
    const int wr = warpId >> 2;
    const int wc = warpId & 3;
    const int m0 = blockIdx.y * 128;
    const int n0 = blockIdx.x * 128;

    idxm[tid] = (float)(tid & 15);

    const int aRow = tid >> 2, aC = (tid & 3) * 4;
    const int bRow = tid >> 5, bC = (tid & 31) * 4;

    auto issue_tile = [&](int k0, int buf) {
#pragma unroll
        for (int t = 0; t < 2; t++) {
            int r = aRow + t * 64;
            cp_async16(&As[buf][r][aC], A + (size_t)(m0 + r) * D + k0 + aC);
        }
#pragma unroll
        for (int t = 0; t < 2; t++) {
            int r = bRow + t * 8;
            cp_async16(&Bs[buf][r][bC], W + (size_t)(k0 + r) * D + n0 + bC);
        }
        cp_commit();
    };

    FragC acc[4][2];
#pragma unroll
    for (int i = 0; i < 4; i++)
#pragma unroll
        for (int j = 0; j < 2; j++) wmma::fill_fragment(acc[i][j], 0.f);

    issue_tile(0, 0);
    __syncthreads();                 // idxm visible
    FragC colidx;
    wmma::load_matrix_sync(colidx, idxm, 16, wmma::mem_row_major);

    constexpr int NIT = cfg::D / 16;     // 64
    for (int kt = 0; kt < NIT; kt++) {
        const int buf = kt & 1;
        if (kt + 1 < NIT) issue_tile((kt + 1) * 16, buf ^ 1);
        if (kt + 1 < NIT) cp_wait<1>(); else cp_wait<0>();
        __syncthreads();

#pragma unroll
        for (int kk = 0; kk < 2; kk++) {
            FragA af[4];
#pragma unroll
            for (int i = 0; i < 4; i++) {
                wmma::load_matrix_sync(af[i], &As[buf][64 * wr + 16 * i][8 * kk], 20);
                to_tf32(af[i]);
            }
            FragBr bf[2];
#pragma unroll
            for (int j = 0; j < 2; j++) {
                wmma::load_matrix_sync(bf[j], &Bs[buf][8 * kk][32 * wc + 16 * j], 132);
                to_tf32(bf[j]);
            }
#pragma unroll
            for (int i = 0; i < 4; i++)
#pragma unroll
                for (int j = 0; j < 2; j++)
                    wmma::mma_sync(acc[i][j], af[i], bf[j], acc[i][j]);
        }
        __syncthreads();             // readers done before buf is overwritten
    }

#pragma unroll
    for (int i = 0; i < 4; i++)
#pragma unroll
        for (int j = 0; j < 2; j++) {
            const int nbase = n0 + 32 * wc + 16 * j;
#pragma unroll
            for (int e = 0; e < 8; e++)
                acc[i][j].x[e] += __ldg(&bias[nbase + (int)colidx.x[e]]);
            wmma::store_matrix_sync(
                C + (size_t)(m0 + 64 * wr + 16 * i) * D + nbase,
                acc[i][j], D, wmma::mem_row_major);
        }
}

// fused QKV projection: blockIdx.z selects input/weight/output
__global__ void __launch_bounds__(256)
gemm_qkv_kernel(const float* __restrict__ q, const float* __restrict__ k,
                const float* __restrict__ v,
                const float* __restrict__ Wq, const float* __restrict__ Wk,
                const float* __restrict__ Wv,
                const float* __restrict__ bq, const float* __restrict__ bk,
                const float* __restrict__ bv,
                float* __restrict__ oq, float* __restrict__ ok,
                float* __restrict__ ov)
{
    const float *A, *W, *bias; float* C;
    if (blockIdx.z == 0)      { A = q; W = Wq; bias = bq; C = oq; }
    else if (blockIdx.z == 1) { A = k; W = Wk; bias = bk; C = ok; }
    else                      { A = v; W = Wv; bias = bv; C = ov; }
    gemm_body(A, W, bias, C);
}

__global__ void __launch_bounds__(256)
gemm_single_kernel(const float* __restrict__ A, const float* __restrict__ W,
                   const float* __restrict__ bias, float* __restrict__ C)
{
    gemm_body(A, W, bias, C);
}

// ----------------------------- tf32 flash attention --------------------------
// grid (T/128, H, B), 256 threads = 8 warps; warp w owns rows 16w..16w+15.
// K/V tiles 64 keys, double-buffered via cp.async.
__global__ void __launch_bounds__(256)
flash_tf32_kernel(const float* __restrict__ Q, const float* __restrict__ K,
                  const float* __restrict__ V, float* __restrict__ O)
{
    using namespace cfg;
    extern __shared__ float sm[];
    float* Ks     = sm;                               // [2][64][FL_LD]
    float* Vs     = sm + FL_KS;                       // [2][64][FL_LD]
    float* Ss     = sm + FL_KS + FL_VS;               // [128][FL_LD]
    float* m_s    = Ss + FL_SS;                       // [128]
    float* l_s    = m_s + 128;
    float* corr_s = l_s + 128;
    float* idxm   = corr_s + 128;                     // [256]

    const int b = blockIdx.z, h = blockIdx.y, q0 = blockIdx.x * 128;
    const int tid = threadIdx.x;
    const int w = tid >> 5;                           // warp -> rows 16w
    const float gscale = g_scale_val;

    const float* Kp = K + (size_t)b * S * D + h * DH;
    const float* Vp = V + (size_t)b * S * D + h * DH;

    idxm[tid] = (float)(tid >> 4);
    if (tid < 128) { m_s[tid] = -INFINITY; l_s[tid] = 0.f; }

    // stage Q tile (128 x 64) into Ss: 2 threads/row, 32 floats each
    {
        const int r = tid >> 1, half = tid & 1;
        const float* src = Q + (size_t)(b * T + q0 + r) * D + h * DH + half * 32;
        float* dst = &Ss[r * FL_LD + half * 32];
#pragma unroll
        for (int jj = 0; jj < 8; jj++)
            *(float4*)(dst + jj * 4) = *(const float4*)(src + jj * 4);
    }
    __syncthreads();

    FragC rowidx;
    wmma::load_matrix_sync(rowidx, idxm, 16, wmma::mem_row_major);

    FragA qf[8];
#pragma unroll
    for (int k = 0; k < 8; k++) {
        wmma::load_matrix_sync(qf[k], &Ss[(16 * w) * FL_LD + 8 * k], FL_LD);
        to_tf32(qf[k]);
    }
    FragC of[4];
#pragma unroll
    for (int j = 0; j < 4; j++) wmma::fill_fragment(of[j], 0.f);
    __syncthreads();                 // Q staging reads finished before Ss reuse

    // K/V tile loader: 64 rows x 64 floats each => 4 chunks/thread/array
    auto issue_kv = [&](int s0, int buf) {
        float* kb = Ks + buf * 64 * FL_LD;
        float* vb = Vs + buf * 64 * FL_LD;
#pragma unroll
        for (int t = 0; t < 4; t++) {
            int c = tid + t * 256;                   // 0..1023
            int row = c >> 4, col = (c & 15) * 4;
            cp_async16(&kb[row * FL_LD + col], Kp + (size_t)(s0 + row) * D + col);
        }
#pragma unroll
        for (int t = 0; t < 4; t++) {
            int c = tid + t * 256;
            int row = c >> 4, col = (c & 15) * 4;
            cp_async16(&vb[row * FL_LD + col], Vp + (size_t)(s0 + row) * D + col);
        }
        cp_commit();
    };

    issue_kv(0, 0);

    constexpr int NT = cfg::S / 64;                  // 32
    for (int it = 0; it < NT; it++) {
        const int buf = it & 1;
        if (it + 1 < NT) issue_kv((it + 1) * 64, buf ^ 1);
        if (it + 1 < NT) cp_wait<1>(); else cp_wait<0>();
        __syncthreads();

        // ---- S = Q K^T
        const float* kb = Ks + buf * 64 * FL_LD;
        FragC sf[4];
#pragma unroll
        for (int j = 0; j < 4; j++) wmma::fill_fragment(sf[j], 0.f);
#pragma unroll
        for (int k = 0; k < 8; k++) {
#pragma unroll
            for (int j = 0; j < 4; j++) {
                FragBc bf;
                wmma::load_matrix_sync(bf, &kb[(16 * j) * FL_LD + 8 * k], FL_LD);
                to_tf32(bf);
                wmma::mma_sync(sf[j], qf[k], bf, sf[j]);
            }
        }
#pragma unroll
        for (int j = 0; j < 4; j++)
            wmma::store_matrix_sync(&Ss[(16 * w) * FL_LD + 16 * j], sf[j],
                                    FL_LD, wmma::mem_row_major);
        __syncthreads();

        // ---- online softmax: 2 threads per row, 32 cols each
        {
            const int r = tid >> 1, half = tid & 1;
            float* row = &Ss[r * FL_LD + half * 32];
            float v[32];
#pragma unroll
            for (int jj = 0; jj < 8; jj++) {
                float4 x = *(float4*)(row + jj * 4);
                v[jj * 4 + 0] = x.x * gscale; v[jj * 4 + 1] = x.y * gscale;
                v[jj * 4 + 2] = x.z * gscale; v[jj * 4 + 3] = x.w * gscale;
            }
            float mx = v[0];
#pragma unroll
            for (int i = 1; i < 32; i++) mx = fmaxf(mx, v[i]);
            mx = fmaxf(mx, __shfl_xor_sync(0xffffffffu, mx, 1));

            const float mold = m_s[r];
            const float nm = fmaxf(mold, mx);
            float sum = 0.f;
#pragma unroll
            for (int i = 0; i < 32; i++) { v[i] = __expf(v[i] - nm); sum += v[i]; }
#pragma unroll
            for (int jj = 0; jj < 8; jj++)
                *(float4*)(row + jj * 4) =
                    make_float4(v[jj * 4 + 0], v[jj * 4 + 1],
                                v[jj * 4 + 2], v[jj * 4 + 3]);
            sum += __shfl_xor_sync(0xffffffffu, sum, 1);
            if (half == 0) {
                float corr = __expf(mold - nm);
                l_s[r] = l_s[r] * corr + sum;
                m_s[r] = nm;
                corr_s[r] = corr;
            }
        }
        __syncthreads();

        // ---- rescale O accumulators
#pragma unroll
        for (int j = 0; j < 4; j++)
#pragma unroll
            for (int e = 0; e < 8; e++)
                of[j].x[e] *= corr_s[16 * w + (int)rowidx.x[e]];

        // ---- O += P V
        const float* vb = Vs + buf * 64 * FL_LD;
#pragma unroll
        for (int k = 0; k < 8; k++) {
            FragA pf;
            wmma::load_matrix_sync(pf, &Ss[(16 * w) * FL_LD + 8 * k], FL_LD);
            to_tf32(pf);
#pragma unroll
            for (int j = 0; j < 4; j++) {
                FragBr vf;
                wmma::load_matrix_sync(vf, &vb[(8 * k) * FL_LD + 16 * j], FL_LD);
                to_tf32(vf);
                wmma::mma_sync(of[j], pf, vf, of[j]);
            }
        }
        __syncthreads();   // Ss / Vs[buf] free before next tile's writes
    }

    // epilogue
    if (tid < 128) corr_s[tid] = 1.0f / l_s[tid];
    __syncthreads();
#pragma unroll
    for (int j = 0; j < 4; j++) {
#pragma unroll
        for (int e = 0; e < 8; e++)
            of[j].x[e] *= corr_s[16 * w + (int)rowidx.x[e]];
        wmma::store_matrix_sync(
            O + (size_t)(b * T + q0 + 16 * w) * D + h * DH + 16 * j,
            of[j], D, wmma::mem_row_major);
    }
}

// ----------------------------- launch ----------------------------------------
extern "C" void kernel_launch(void* const* d_in, const int* in_sizes, int n_in,
                              void* d_out, int out_size)
{
    using namespace cfg;
    (void)in_sizes; (void)n_in; (void)out_size;

    const float* query  = (const float*)d_in[0];
    const float* key    = (const float*)d_in[1];
    const float* value  = (const float*)d_in[2];
    const float* memory = (const float*)d_in[3];
    const float* Wq = (const float*)d_in[4];
    const float* bq = (const float*)d_in[5];
    const float* Wk = (const float*)d_in[6];
    const float* bk = (const float*)d_in[7];
    const float* Wv = (const float*)d_in[8];
    const float* bv = (const float*)d_in[9];
    const float* Wo = (const float*)d_in[10];
    const float* bo = (const float*)d_in[11];
    const float* Wg = (const float*)d_in[12];
    const float* bg = (const float*)d_in[13];
    float* out = (float*)d_out;

    void *pQ, *pK, *pV, *pO;
    cudaGetSymbolAddress(&pQ, g_Q);
    cudaGetSymbolAddress(&pK, g_K);
    cudaGetSymbolAddress(&pV, g_V);
    cudaGetSymbolAddress(&pO, g_O);

    cudaFuncSetAttribute(flash_tf32_kernel,
                         cudaFuncAttributeMaxDynamicSharedMemorySize, FL_SMEM);

    // gate path
    mean_kernel<<<dim3(D / 256, B), 256>>>(query, memory);
    gate_vals_kernel<<<dim3(D / 256, B), 256>>>(Wg, bg);
    gate_reduce_kernel<<<1, 1024>>>();

    // fused QKV projections
    gemm_qkv_kernel<<<dim3(D / 128, BT / 128, 3), 256>>>(
        query, key, value, Wq, Wk, Wv, bq, bk, bv,
        (float*)pQ, (float*)pK, (float*)pV);

    // attention
    flash_tf32_kernel<<<dim3(T / 128, H, B), 256, FL_SMEM>>>(
        (const float*)pQ, (const float*)pK, (const float*)pV, (float*)pO);

    // output projection -> d_out
    gemm_single_kernel<<<dim3(D / 128, BT / 128), 256>>>(
        (const float*)pO, Wo, bo, out);
}

// round 7
// speedup vs baseline: 2.7829x; 2.7829x over previous
#include <cuda_runtime.h>
#include <cuda_fp16.h>
#include <mma.h>
#include <math.h>

using namespace nvcuda;

// ---------------------------------------------------------------------------
// MemoryGatedAttention  (B=4, T=S=2048, D=1024, H=16, DH=64, M=64)
// Round 7: fp16 HMMA everywhere (same 10-bit mantissa as tf32, 2x rate,
// half the smem traffic). fp32 softmax/accum. cp.async double buffering.
// ---------------------------------------------------------------------------

namespace cfg {
constexpr int B  = 4;
constexpr int T  = 2048;
constexpr int S  = 2048;
constexpr int D  = 1024;
constexpr int H  = 16;
constexpr int DH = 64;
constexpr int M  = 64;
constexpr int BT = B * T;
// flash smem layout (bytes):
constexpr int LDH = 72;                       // half stride for K/V/P tiles
constexpr int LDS = 68;                       // float stride for S tile
constexpr int FL_KS_H   = 2 * 64 * LDH;       // halves
constexpr int FL_VS_H   = 2 * 64 * LDH;
constexpr int FL_PS_H   = 128 * LDH;
constexpr int FL_SS_F   = 128 * LDS;          // floats
constexpr int FL_BYTES  = (FL_KS_H + FL_VS_H + FL_PS_H) * 2
                        + FL_SS_F * 4 + (3 * 128 + 256) * 4;   // ~92.7KB
}

// ----------------------------- scratch --------------------------------------
__device__ __half g_qh[cfg::BT * cfg::D];
__device__ __half g_kh[cfg::BT * cfg::D];
__device__ __half g_vh[cfg::BT * cfg::D];
__device__ __half g_Wqh[cfg::D * cfg::D];
__device__ __half g_Wkh[cfg::D * cfg::D];
__device__ __half g_Wvh[cfg::D * cfg::D];
__device__ __half g_Woh[cfg::D * cfg::D];
__device__ __half g_Qh[cfg::BT * cfg::D];
__device__ __half g_Kh[cfg::BT * cfg::D];
__device__ __half g_Vh[cfg::BT * cfg::D];
__device__ __half g_Oh[cfg::BT * cfg::D];
__device__ float  g_memin[cfg::B * 2 * cfg::D];
__device__ float  g_gatevals[cfg::B * cfg::D];
__device__ float  g_scale_val;

// ----------------------------- cp.async helpers ------------------------------
__device__ __forceinline__ void cp_async16(void* smem_dst, const void* gmem_src) {
    unsigned sa = (unsigned)__cvta_generic_to_shared(smem_dst);
    asm volatile("cp.async.cg.shared.global [%0], [%1], 16;\n" :: "r"(sa), "l"(gmem_src));
}
__device__ __forceinline__ void cp_commit() {
    asm volatile("cp.async.commit_group;\n");
}
template <int N>
__device__ __forceinline__ void cp_wait() {
    asm volatile("cp.async.wait_group %0;\n" :: "n"(N));
}

// ----------------------------- fragment types --------------------------------
using HFragA  = wmma::fragment<wmma::matrix_a, 16, 16, 16, __half, wmma::row_major>;
using HFragBr = wmma::fragment<wmma::matrix_b, 16, 16, 16, __half, wmma::row_major>;
using HFragBc = wmma::fragment<wmma::matrix_b, 16, 16, 16, __half, wmma::col_major>;
using HFragC  = wmma::fragment<wmma::accumulator, 16, 16, 16, float>;

// ----------------------------- f32 -> f16 convert ----------------------------
__global__ void __launch_bounds__(256)
cvt_kernel(const float* __restrict__ src, __half* __restrict__ dst, int n)
{
    int i = (blockIdx.x * 256 + threadIdx.x) * 8;
    if (i >= n) return;
    float4 a = *(const float4*)(src + i);
    float4 b = *(const float4*)(src + i + 4);
    __half2 h0 = __floats2half2_rn(a.x, a.y);
    __half2 h1 = __floats2half2_rn(a.z, a.w);
    __half2 h2 = __floats2half2_rn(b.x, b.y);
    __half2 h3 = __floats2half2_rn(b.z, b.w);
    uint4 u;
    u.x = *(unsigned*)&h0; u.y = *(unsigned*)&h1;
    u.z = *(unsigned*)&h2; u.w = *(unsigned*)&h3;
    *(uint4*)(dst + i) = u;
}

// ----------------------------- means ----------------------------------------
__global__ void __launch_bounds__(256)
mean_kernel(const float* __restrict__ query, const float* __restrict__ memory)
{
    using namespace cfg;
    const int b = blockIdx.y;
    const int d = blockIdx.x * blockDim.x + threadIdx.x;

    const float* qp = query + (size_t)b * T * D + d;
    float s0 = 0.f, s1 = 0.f, s2 = 0.f, s3 = 0.f;
    for (int t = 0; t < T; t += 4) {
        s0 += qp[(size_t)(t + 0) * D];
        s1 += qp[(size_t)(t + 1) * D];
        s2 += qp[(size_t)(t + 2) * D];
        s3 += qp[(size_t)(t + 3) * D];
    }
    g_memin[b * 2 * D + d] = ((s0 + s1) + (s2 + s3)) * (1.0f / T);

    const float* mp = memory + (size_t)b * M * D + d;
    float u0 = 0.f, u1 = 0.f;
    for (int m = 0; m < M; m += 2) {
        u0 += mp[(size_t)(m + 0) * D];
        u1 += mp[(size_t)(m + 1) * D];
    }
    g_memin[b * 2 * D + D + d] = (u0 + u1) * (1.0f / M);
}

// ----------------------------- gate ------------------------------------------
__global__ void __launch_bounds__(256)
gate_vals_kernel(const float* __restrict__ Wg, const float* __restrict__ bg)
{
    using namespace cfg;
    const int b = blockIdx.y;
    const int j = blockIdx.x * blockDim.x + threadIdx.x;
    const float* mi = g_memin + b * 2 * D;

    float a0 = 0.f, a1 = 0.f, a2 = 0.f, a3 = 0.f;
    for (int i = 0; i < 2 * D; i += 4) {
        a0 += mi[i + 0] * Wg[(size_t)(i + 0) * D + j];
        a1 += mi[i + 1] * Wg[(size_t)(i + 1) * D + j];
        a2 += mi[i + 2] * Wg[(size_t)(i + 2) * D + j];
        a3 += mi[i + 3] * Wg[(size_t)(i + 3) * D + j];
    }
    float acc = bg[j] + ((a0 + a1) + (a2 + a3));
    g_gatevals[b * D + j] = 1.0f / (1.0f + expf(-acc));
}

__global__ void gate_reduce_kernel()
{
    using namespace cfg;
    __shared__ float red[1024];
    const int t = threadIdx.x;
    red[t] = g_gatevals[t] + g_gatevals[t + 1024] +
             g_gatevals[t + 2048] + g_gatevals[t + 3072];
    __syncthreads();
    for (int s = 512; s > 0; s >>= 1) {
        if (t < s) red[t] += red[t + s];
        __syncthreads();
    }
    if (t == 0) g_scale_val = red[0] * (1.0f / (B * D)) * 0.125f;
}

// ----------------------------- fp16 GEMM body --------------------------------
// C = A[8192,1024] @ W[1024,1024] + bias.  128x128 block, BK=32, 8 warps(2x4),
// warp tile 64x32 = 4x2 m16n16k16 fragments. cp.async double buffered.
// HALF_OUT: scatter-store half via index fragment; else fp32 store_matrix_sync.
template <bool HALF_OUT>
__device__ __forceinline__ void gemm_body_h(
    const __half* __restrict__ A, const __half* __restrict__ W,
    const float* __restrict__ bias, __half* __restrict__ Ch,
    float* __restrict__ Cf)
{
    using namespace cfg;
    __shared__ __half As[2][128][40];      // [m][k] pad 8 halves
    __shared__ __half Bs[2][32][136];      // [k][n] pad 8 halves
    __shared__ float idxm[256];

    const int tid = threadIdx.x;
    const int warpId = tid >> 5;
    const int wr = warpId >> 2;            // 0..1
    const int wc = warpId & 3;             // 0..3
    const int m0 = blockIdx.y * 128;
    const int n0 = blockIdx.x * 128;

    idxm[tid] = (float)tid;                // combined (row<<4 | col) in 16x16 tile

    auto issue_tile = [&](int k0, int buf) {
#pragma unroll
        for (int t = 0; t < 2; t++) {
            int c = tid + t * 256;
            int r = c >> 2, cc = (c & 3) * 8;
            cp_async16(&As[buf][r][cc], A + (size_t)(m0 + r) * D + k0 + cc);
        }
#pragma unroll
        for (int t = 0; t < 2; t++) {
            int c = tid + t * 256;
            int r = c >> 4, cc = (c & 15) * 8;
            cp_async16(&Bs[buf][r][cc], W + (size_t)(k0 + r) * D + n0 + cc);
        }
        cp_commit();
    };

    HFragC acc[4][2];
#pragma unroll
    for (int i = 0; i < 4; i++)
#pragma unroll
        for (int j = 0; j < 2; j++) wmma::fill_fragment(acc[i][j], 0.f);

    issue_tile(0, 0);
    __syncthreads();
    HFragC idxf;
    wmma::load_matrix_sync(idxf, idxm, 16, wmma::mem_row_major);

    constexpr int NIT = cfg::D / 32;       // 32
    for (int kt = 0; kt < NIT; kt++) {
        const int buf = kt & 1;
        if (kt + 1 < NIT) issue_tile((kt + 1) * 32, buf ^ 1);
        if (kt + 1 < NIT) cp_wait<1>(); else cp_wait<0>();
        __syncthreads();

#pragma unroll
        for (int kk = 0; kk < 2; kk++) {
            HFragA af[4];
#pragma unroll
            for (int i = 0; i < 4; i++)
                wmma::load_matrix_sync(af[i], &As[buf][64 * wr + 16 * i][16 * kk], 40);
            HFragBr bf[2];
#pragma unroll
            for (int j = 0; j < 2; j++)
                wmma::load_matrix_sync(bf[j], &Bs[buf][16 * kk][32 * wc + 16 * j], 136);
#pragma unroll
            for (int i = 0; i < 4; i++)
#pragma unroll
                for (int j = 0; j < 2; j++)
                    wmma::mma_sync(acc[i][j], af[i], bf[j], acc[i][j]);
        }
        __syncthreads();
    }

#pragma unroll
    for (int i = 0; i < 4; i++)
#pragma unroll
        for (int j = 0; j < 2; j++) {
            const int rbase = m0 + 64 * wr + 16 * i;
            const int cbase = n0 + 32 * wc + 16 * j;
            if (HALF_OUT) {
#pragma unroll
                for (int e = 0; e < 8; e++) {
                    int v = (int)idxf.x[e];
                    int r = v >> 4, c = v & 15;
                    Ch[(size_t)(rbase + r) * D + cbase + c] =
                        __float2half(acc[i][j].x[e] + __ldg(&bias[cbase + c]));
                }
            } else {
#pragma unroll
                for (int e = 0; e < 8; e++)
                    acc[i][j].x[e] += __ldg(&bias[cbase + ((int)idxf.x[e] & 15)]);
                wmma::store_matrix_sync(Cf + (size_t)rbase * D + cbase,
                                        acc[i][j], D, wmma::mem_row_major);
            }
        }
}

// fused QKV projection: blockIdx.z selects input/weight/output
__global__ void __launch_bounds__(256)
gemm_qkv_h_kernel(const float* __restrict__ bq, const float* __restrict__ bk,
                  const float* __restrict__ bv)
{
    const __half *A, *W; const float* bias; __half* C;
    if (blockIdx.z == 0)      { A = g_qh; W = g_Wqh; bias = bq; C = g_Qh; }
    else if (blockIdx.z == 1) { A = g_kh; W = g_Wkh; bias = bk; C = g_Kh; }
    else                      { A = g_vh; W = g_Wvh; bias = bv; C = g_Vh; }
    gemm_body_h<true>(A, W, bias, C, nullptr);
}

__global__ void __launch_bounds__(256)
gemm_out_kernel(const float* __restrict__ bo, float* __restrict__ out)
{
    gemm_body_h<false>(g_Oh, g_Woh, bo, nullptr, out);
}

// ----------------------------- fp16 flash attention --------------------------
// grid (T/128, H, B), 256 threads = 8 warps; warp w owns rows 16w..16w+15.
// K/V tiles 64 keys (half), double-buffered cp.async. S fp32, P half.
__global__ void __launch_bounds__(256)
flash_h_kernel(float* dummy)
{
    using namespace cfg;
    extern __shared__ char smraw[];
    __half* Ks  = (__half*)smraw;                          // [2][64][LDH]
    __half* Vs  = Ks + FL_KS_H;                            // [2][64][LDH]
    __half* Ps  = Vs + FL_VS_H;                            // [128][LDH] (also Q staging)
    float*  Ss  = (float*)(Ps + FL_PS_H);                  // [128][LDS]
    float*  m_s = Ss + FL_SS_F;                            // [128]
    float*  l_s    = m_s + 128;
    float*  corr_s = l_s + 128;
    float*  idxm   = corr_s + 128;                         // [256]

    const int b = blockIdx.z, h = blockIdx.y, q0 = blockIdx.x * 128;
    const int tid = threadIdx.x;
    const int w = tid >> 5;
    const float gscale = g_scale_val;

    const __half* Kp = g_Kh + (size_t)b * S * D + h * DH;
    const __half* Vp = g_Vh + (size_t)b * S * D + h * DH;

    idxm[tid] = (float)tid;
    if (tid < 128) { m_s[tid] = -INFINITY; l_s[tid] = 0.f; }

    // stage Q tile (128 x 64 halves) into Ps: 2 threads/row, 32 halves each
    {
        const int r = tid >> 1, half_ = tid & 1;
        const __half* src = g_Qh + (size_t)(b * T + q0 + r) * D + h * DH + half_ * 32;
        __half* dst = &Ps[r * LDH + half_ * 32];
#pragma unroll
        for (int jj = 0; jj < 4; jj++)
            *(uint4*)(dst + jj * 8) = *(const uint4*)(src + jj * 8);
    }
    __syncthreads();

    HFragC idxf;
    wmma::load_matrix_sync(idxf, idxm, 16, wmma::mem_row_major);

    HFragA qf[4];
#pragma unroll
    for (int k = 0; k < 4; k++)
        wmma::load_matrix_sync(qf[k], &Ps[(16 * w) * LDH + 16 * k], LDH);
    HFragC of[4];
#pragma unroll
    for (int j = 0; j < 4; j++) wmma::fill_fragment(of[j], 0.f);
    __syncthreads();                 // Q reads done before Ps reused for P

    // K/V tile loader: 64 rows x 64 halves = 8 chunks/row -> 2/thread/array
    auto issue_kv = [&](int s0, int buf) {
        __half* kb = Ks + buf * 64 * LDH;
        __half* vb = Vs + buf * 64 * LDH;
#pragma unroll
        for (int t = 0; t < 2; t++) {
            int c = tid + t * 256;
            int row = c >> 3, col = (c & 7) * 8;
            cp_async16(&kb[row * LDH + col], Kp + (size_t)(s0 + row) * D + col);
        }
#pragma unroll
        for (int t = 0; t < 2; t++) {
            int c = tid + t * 256;
            int row = c >> 3, col = (c & 7) * 8;
            cp_async16(&vb[row * LDH + col], Vp + (size_t)(s0 + row) * D + col);
        }
        cp_commit();
    };

    issue_kv(0, 0);

    constexpr int NT = cfg::S / 64;                  // 32
    for (int it = 0; it < NT; it++) {
        const int buf = it & 1;
        if (it + 1 < NT) issue_kv((it + 1) * 64, buf ^ 1);
        if (it + 1 < NT) cp_wait<1>(); else cp_wait<0>();
        __syncthreads();

        // ---- S = Q K^T  (Ks[key][d] -> matrix_b col_major)
        const __half* kb = Ks + buf * 64 * LDH;
        HFragC sf[4];
#pragma unroll
        for (int j = 0; j < 4; j++) wmma::fill_fragment(sf[j], 0.f);
#pragma unroll
        for (int k = 0; k < 4; k++) {
#pragma unroll
            for (int j = 0; j < 4; j++) {
                HFragBc bf;
                wmma::load_matrix_sync(bf, &kb[(16 * j) * LDH + 16 * k], LDH);
                wmma::mma_sync(sf[j], qf[k], bf, sf[j]);
            }
        }
#pragma unroll
        for (int j = 0; j < 4; j++)
            wmma::store_matrix_sync(&Ss[(16 * w) * LDS + 16 * j], sf[j],
                                    LDS, wmma::mem_row_major);
        __syncthreads();

        // ---- online softmax: 2 threads/row, 32 cols each; P -> half
        {
            const int r = tid >> 1, half_ = tid & 1;
            float* row = &Ss[r * LDS + half_ * 32];
            __half* prow = &Ps[r * LDH + half_ * 32];
            float v[32];
#pragma unroll
            for (int jj = 0; jj < 8; jj++) {
                float4 x = *(float4*)(row + jj * 4);
                v[jj * 4 + 0] = x.x * gscale; v[jj * 4 + 1] = x.y * gscale;
                v[jj * 4 + 2] = x.z * gscale; v[jj * 4 + 3] = x.w * gscale;
            }
            float mx = v[0];
#pragma unroll
            for (int i = 1; i < 32; i++) mx = fmaxf(mx, v[i]);
            mx = fmaxf(mx, __shfl_xor_sync(0xffffffffu, mx, 1));

            const float mold = m_s[r];
            const float nm = fmaxf(mold, mx);
            float sum = 0.f;
#pragma unroll
            for (int i = 0; i < 32; i++) { v[i] = __expf(v[i] - nm); sum += v[i]; }
#pragma unroll
            for (int jj = 0; jj < 16; jj++)
                *(__half2*)(prow + jj * 2) = __floats2half2_rn(v[jj * 2], v[jj * 2 + 1]);
            sum += __shfl_xor_sync(0xffffffffu, sum, 1);
            if (half_ == 0) {
                float corr = __expf(mold - nm);
                l_s[r] = l_s[r] * corr + sum;
                m_s[r] = nm;
                corr_s[r] = corr;
            }
        }
        __syncthreads();

        // ---- rescale O accumulators
#pragma unroll
        for (int j = 0; j < 4; j++)
#pragma unroll
            for (int e = 0; e < 8; e++)
                of[j].x[e] *= corr_s[16 * w + ((int)idxf.x[e] >> 4)];

        // ---- O += P V
        const __half* vb = Vs + buf * 64 * LDH;
#pragma unroll
        for (int k = 0; k < 4; k++) {
            HFragA pf;
            wmma::load_matrix_sync(pf, &Ps[(16 * w) * LDH + 16 * k], LDH);
#pragma unroll
            for (int j = 0; j < 4; j++) {
                HFragBr vf;
                wmma::load_matrix_sync(vf, &vb[(16 * k) * LDH + 16 * j], LDH);
                wmma::mma_sync(of[j], pf, vf, of[j]);
            }
        }
        __syncthreads();   // Ps/Ks[buf]/Vs[buf] free before next writes
    }

    // epilogue: normalize rows, scatter-store half O
    if (tid < 128) corr_s[tid] = 1.0f / l_s[tid];
    __syncthreads();
#pragma unroll
    for (int j = 0; j < 4; j++) {
#pragma unroll
        for (int e = 0; e < 8; e++) {
            int v = (int)idxf.x[e];
            int r = v >> 4, c = v & 15;
            g_Oh[(size_t)(b * T + q0 + 16 * w + r) * D + h * DH + 16 * j + c] =
                __float2half(of[j].x[e] * corr_s[16 * w + r]);
        }
    }
    (void)dummy;
}

// ----------------------------- launch ----------------------------------------
extern "C" void kernel_launch(void* const* d_in, const int* in_sizes, int n_in,
                              void* d_out, int out_size)
{
    using namespace cfg;
    (void)in_sizes; (void)n_in; (void)out_size;

    const float* query  = (const float*)d_in[0];
    const float* key    = (const float*)d_in[1];
    const float* value  = (const float*)d_in[2];
    const float* memory = (const float*)d_in[3];
    const float* Wq = (const float*)d_in[4];
    const float* bq = (const float*)d_in[5];
    const float* Wk = (const float*)d_in[6];
    const float* bk = (const float*)d_in[7];
    const float* Wv = (const float*)d_in[8];
    const float* bv = (const float*)d_in[9];
    const float* Wo = (const float*)d_in[10];
    const float* bo = (const float*)d_in[11];
    const float* Wg = (const float*)d_in[12];
    const float* bg = (const float*)d_in[13];
    float* out = (float*)d_out;

    void *qh, *kh, *vh, *wqh, *wkh, *wvh, *woh;
    cudaGetSymbolAddress(&qh,  g_qh);
    cudaGetSymbolAddress(&kh,  g_kh);
    cudaGetSymbolAddress(&vh,  g_vh);
    cudaGetSymbolAddress(&wqh, g_Wqh);
    cudaGetSymbolAddress(&wkh, g_Wkh);
    cudaGetSymbolAddress(&wvh, g_Wvh);
    cudaGetSymbolAddress(&woh, g_Woh);

    cudaFuncSetAttribute(flash_h_kernel,
                         cudaFuncAttributeMaxDynamicSharedMemorySize, FL_BYTES);

    // gate path (fp32, independent)
    mean_kernel<<<dim3(D / 256, B), 256>>>(query, memory);
    gate_vals_kernel<<<dim3(D / 256, B), 256>>>(Wg, bg);
    gate_reduce_kernel<<<1, 1024>>>();

    // convert inputs + weights to half
    const int nBig = BT * D;          // 8M
    const int nW   = D * D;           // 1M
    cvt_kernel<<<nBig / (256 * 8), 256>>>(query, (__half*)qh, nBig);
    cvt_kernel<<<nBig / (256 * 8), 256>>>(key,   (__half*)kh, nBig);
    cvt_kernel<<<nBig / (256 * 8), 256>>>(value, (__half*)vh, nBig);
    cvt_kernel<<<nW / (256 * 8), 256>>>(Wq, (__half*)wqh, nW);
    cvt_kernel<<<nW / (256 * 8), 256>>>(Wk, (__half*)wkh, nW);
    cvt_kernel<<<nW / (256 * 8), 256>>>(Wv, (__half*)wvh, nW);
    cvt_kernel<<<nW / (256 * 8), 256>>>(Wo, (__half*)woh, nW);

    // fused QKV projections (fp16 tensor cores)
    gemm_qkv_h_kernel<<<dim3(D / 128, BT / 128, 3), 256>>>(bq, bk, bv);

    // attention (fp16 tensor cores)
    flash_h_kernel<<<dim3(T / 128, H, B), 256, FL_BYTES>>>(nullptr);

    // output projection -> d_out (fp32 out)
    gemm_out_kernel<<<dim3(D / 128, BT / 128), 256>>>(bo, out);
}